// round 3
// baseline (speedup 1.0000x reference)
#include <cuda_runtime.h>
#include <cuda_fp16.h>
#include <cstdint>
#include <cstddef>

#define N_NODES 10000
#define EMBED   300
#define HID     256

// big GEMM tiling
#define BM      80        // 125 * 80 = 10000 exactly -> no tail, single wave
#define BK      64        // 64 fp16 = 128B row (SW128 swizzle atom)
#define NKCH    157       // ceil(10000/64)
#define STAGES  4

#define ADJ_SCALE  16384.0f          // lift adj out of fp16-subnormal range (2^14)
#define ADJ_INV    6.103515625e-05f  // 2^-14

// ---- dynamic smem layout for big GEMM ----
#define SM_BIAS   0                           // 256 floats
#define A_BYTES   (BM  * BK * 2)              // 10240
#define B_BYTES   (256 * BK * 2)              // 32768
#define STG_BYTES (A_BYTES + B_BYTES)         // 43008
#define SM_A(s)   (1024 + (s) * STG_BYTES)
#define SM_B(s)   (SM_A(s) + A_BYTES)
#define SMEM_BYTES (1024 + STAGES * STG_BYTES)  // 173056

// ---- device scratch (allocation-free rule: __device__ globals) ----
__device__ __align__(1024) __half g_adjh[(size_t)N_NODES * N_NODES]; // adj * 2^14, fp16 (200 MB)
__device__ __align__(1024) float  g_x   [N_NODES * EMBED];           // gather+max result
__device__ __align__(1024) __half g_yTh [HID * N_NODES];             // (X@W)^T fp16, K-major B
__device__ __align__(1024) float  g_h1  [N_NODES * HID];             // layer-1 activations

// ---------------------------------------------------------------------------
static __device__ __forceinline__ uint32_t smem_u32(const void* p) {
    uint32_t a;
    asm("{ .reg .u64 t; cvta.to.shared.u64 t, %1; cvt.u32.u64 %0, t; }" : "=r"(a) : "l"(p));
    return a;
}
#define SWZ(b) ((b) ^ (((b) >> 3) & 0x70))

static __device__ __forceinline__ void cp_async16(uint32_t dst, const void* src, uint32_t nbytes) {
    asm volatile("cp.async.cg.shared.global [%0], [%1], 16, %2;"
        :: "r"(dst), "l"(src), "r"(nbytes) : "memory");
}
#define CP_COMMIT() asm volatile("cp.async.commit_group;" ::: "memory")

static __device__ __forceinline__ void ldsm_x4(uint32_t r[4], uint32_t addr) {
    asm volatile("ldmatrix.sync.aligned.m8n8.x4.shared.b16 {%0,%1,%2,%3}, [%4];"
        : "=r"(r[0]), "=r"(r[1]), "=r"(r[2]), "=r"(r[3]) : "r"(addr));
}
static __device__ __forceinline__ void mma16816(float c[4], const uint32_t a[4],
                                                uint32_t b0, uint32_t b1) {
    asm volatile("mma.sync.aligned.m16n8k16.row.col.f32.f16.f16.f32 "
        "{%0,%1,%2,%3}, {%4,%5,%6,%7}, {%8,%9}, {%0,%1,%2,%3};"
        : "+f"(c[0]), "+f"(c[1]), "+f"(c[2]), "+f"(c[3])
        : "r"(a[0]), "r"(a[1]), "r"(a[2]), "r"(a[3]), "r"(b0), "r"(b1));
}

// ---------------------------------------------------------------------------
// Kernel 0: adj (fp32) -> g_adjh (fp16, scaled by 2^14). 8 elems/thread.
// ---------------------------------------------------------------------------
__global__ void __launch_bounds__(256) convert_adj_kernel(const float* __restrict__ adj) {
    size_t i = ((size_t)blockIdx.x * 256 + threadIdx.x) * 8;
    if (i >= (size_t)N_NODES * N_NODES) return;
    float4 v0 = *(const float4*)(adj + i);
    float4 v1 = *(const float4*)(adj + i + 4);
    __half2 h[4];
    h[0] = __floats2half2_rn(v0.x * ADJ_SCALE, v0.y * ADJ_SCALE);
    h[1] = __floats2half2_rn(v0.z * ADJ_SCALE, v0.w * ADJ_SCALE);
    h[2] = __floats2half2_rn(v1.x * ADJ_SCALE, v1.y * ADJ_SCALE);
    h[3] = __floats2half2_rn(v1.z * ADJ_SCALE, v1.w * ADJ_SCALE);
    *(uint4*)(g_adjh + i) = *(uint4*)h;
}

// ---------------------------------------------------------------------------
// Kernel 1: gather + max over REP=8 embeddings
// ---------------------------------------------------------------------------
__global__ void gather_max_kernel(const int* __restrict__ nodes, const float* __restrict__ emb) {
    int m = blockIdx.x;
    __shared__ int idx[8];
    if (threadIdx.x < 8) idx[threadIdx.x] = nodes[(m + 1) * 8 + threadIdx.x];
    __syncthreads();
    for (int e = threadIdx.x; e < EMBED / 4; e += blockDim.x) {
        float4 mx = *(const float4*)(emb + (size_t)idx[0] * EMBED + e * 4);
        #pragma unroll
        for (int r = 1; r < 8; ++r) {
            float4 v = *(const float4*)(emb + (size_t)idx[r] * EMBED + e * 4);
            mx.x = fmaxf(mx.x, v.x); mx.y = fmaxf(mx.y, v.y);
            mx.z = fmaxf(mx.z, v.z); mx.w = fmaxf(mx.w, v.w);
        }
        *(float4*)(g_x + (size_t)m * EMBED + e * 4) = mx;
    }
}

// ---------------------------------------------------------------------------
// Kernel 2: small GEMM (exact fp32):  g_yTh[n][m] = fp16_rn( (X @ W)[m][n] )
// ---------------------------------------------------------------------------
__global__ void __launch_bounds__(256) small_gemm_kernel(const float* __restrict__ W, int K, int layer) {
    __shared__ float xs[32][17];
    __shared__ float ws[16][256];
    const float* X = layer ? g_h1 : g_x;
    int ldx = layer ? HID : EMBED;
    int m0 = blockIdx.x * 32;
    int tid = threadIdx.x;
    int tr = tid >> 6, tc = tid & 63;
    float acc[8][4] = {};

    for (int k0 = 0; k0 < K; k0 += 16) {
        #pragma unroll
        for (int j = 0; j < 2; ++j) {
            int idx = tid + j * 256; int r = idx >> 4, c = idx & 15;
            int gm = m0 + r, gk = k0 + c;
            xs[r][c] = (gm < N_NODES && gk < K) ? X[(size_t)gm * ldx + gk] : 0.0f;
        }
        #pragma unroll
        for (int j = 0; j < 4; ++j) {
            int idx = tid + j * 256; int r = idx >> 6, c4 = idx & 63;
            float4 v = make_float4(0.f, 0.f, 0.f, 0.f);
            if (k0 + r < K) v = *(const float4*)(W + (size_t)(k0 + r) * HID + c4 * 4);
            *(float4*)&ws[r][c4 * 4] = v;
        }
        __syncthreads();
        #pragma unroll
        for (int kk = 0; kk < 16; ++kk) {
            float4 w = *(const float4*)&ws[kk][tc * 4];
            #pragma unroll
            for (int i = 0; i < 8; ++i) {
                float xv = xs[tr * 8 + i][kk];
                acc[i][0] += xv * w.x; acc[i][1] += xv * w.y;
                acc[i][2] += xv * w.z; acc[i][3] += xv * w.w;
            }
        }
        __syncthreads();
    }
    #pragma unroll
    for (int i = 0; i < 8; ++i) {
        int m = m0 + tr * 8 + i;
        if (m < N_NODES) {
            #pragma unroll
            for (int j = 0; j < 4; ++j)
                g_yTh[(size_t)(tc * 4 + j) * N_NODES + m] = __float2half_rn(acc[i][j]);
        }
    }
}

// ---------------------------------------------------------------------------
// Kernel 3: big GEMM via mma.sync (fp16 in, fp32 accum)
//   out[m][n] = leaky_relu( (sum_k adjh[m][k]*yTh[n][k]) * 2^-14 + bias[n] )
// BM=80 x BN=256 per CTA, BK=64, 4-stage cp.async. 8 warps: warp w owns n in
// [32w, 32w+32). Warp tile 80x32: 5 m16-frags x 4 n8-frags, 80 accum regs.
// ---------------------------------------------------------------------------
__global__ void __launch_bounds__(256, 1)
big_gemm_kernel(const float* __restrict__ bias, float* __restrict__ dout) {
    extern __shared__ char smem[];
    uint32_t sb = smem_u32(smem);
    int tid = threadIdx.x;
    int w = tid >> 5, lane = tid & 31;
    float* out = dout ? dout : g_h1;
    int m0 = blockIdx.x * BM;

    ((float*)(smem + SM_BIAS))[tid] = bias[tid];

    float acc[5][4][4];
    #pragma unroll
    for (int a = 0; a < 5; ++a)
        #pragma unroll
        for (int b = 0; b < 4; ++b)
            #pragma unroll
            for (int c = 0; c < 4; ++c) acc[a][b][c] = 0.f;

    // ---- producer helper (inlined twice) ----
    auto fill = [&](int chunk) {
        int s = chunk & (STAGES - 1);
        int k0 = chunk * BK;
        uint32_t sa = sb + SM_A(s), sB = sb + SM_B(s);
        // A: 80 rows x 8 x 16B = 640 units
        #pragma unroll
        for (int i = 0; i < 3; ++i) {
            int c = tid + i * 256;
            if (c < 640) {
                int row = c >> 3, ch = c & 7;
                int kk = k0 + ch * 8;
                int ok = kk < N_NODES;
                const __half* g = g_adjh + (size_t)(m0 + row) * N_NODES + (ok ? kk : 0);
                cp_async16(sa + SWZ(row * 128 + ch * 16), g, ok ? 16u : 0u);
            }
        }
        // B: 256 rows x 8 x 16B = 2048 units
        #pragma unroll
        for (int i = 0; i < 8; ++i) {
            int c = tid + i * 256;
            int row = c >> 3, ch = c & 7;
            int kk = k0 + ch * 8;
            int ok = kk < N_NODES;
            const __half* g = g_yTh + (size_t)row * N_NODES + (ok ? kk : 0);
            cp_async16(sB + SWZ(row * 128 + ch * 16), g, ok ? 16u : 0u);
        }
        CP_COMMIT();
    };

    // prologue: stages 0..2
    fill(0); fill(1); fill(2);

    for (int j = 0; j < NKCH; ++j) {
        asm volatile("cp.async.wait_group %0;" :: "n"(STAGES - 2));
        __syncthreads();
        int s = j & (STAGES - 1);
        uint32_t sa = sb + SM_A(s), sB = sb + SM_B(s);
        #pragma unroll
        for (int ks = 0; ks < 4; ++ks) {
            uint32_t af[5][4];
            #pragma unroll
            for (int mt = 0; mt < 5; ++mt) {
                uint32_t off = (uint32_t)(mt * 16 + (lane & 15)) * 128 + ks * 32 + (lane >> 4) * 16;
                ldsm_x4(af[mt], sa + SWZ(off));
            }
            uint32_t bf[2][4];
            #pragma unroll
            for (int e = 0; e < 2; ++e) {
                uint32_t row = w * 32 + e * 16 + ((lane >> 4) & 1) * 8 + (lane & 7);
                uint32_t off = row * 128 + ks * 32 + ((lane >> 3) & 1) * 16;
                ldsm_x4(bf[e], sB + SWZ(off));
            }
            #pragma unroll
            for (int mt = 0; mt < 5; ++mt)
                #pragma unroll
                for (int nt = 0; nt < 4; ++nt)
                    mma16816(acc[mt][nt], af[mt], bf[nt >> 1][(nt & 1) * 2], bf[nt >> 1][(nt & 1) * 2 + 1]);
        }
        __syncthreads();
        if (j + 3 < NKCH) fill(j + 3); else CP_COMMIT();
    }

    // ---- epilogue: unscale, bias, leaky_relu, store fp32 ----
    const float* bsm = (const float*)(smem + SM_BIAS);
    int qr = lane >> 2, qc = lane & 3;
    #pragma unroll
    for (int mt = 0; mt < 5; ++mt) {
        int r0 = m0 + mt * 16 + qr;
        #pragma unroll
        for (int nt = 0; nt < 4; ++nt) {
            int col = w * 32 + nt * 8 + qc * 2;
            float b0 = bsm[col], b1 = bsm[col + 1];
            float v0 = acc[mt][nt][0] * ADJ_INV + b0;
            float v1 = acc[mt][nt][1] * ADJ_INV + b1;
            float v2 = acc[mt][nt][2] * ADJ_INV + b0;
            float v3 = acc[mt][nt][3] * ADJ_INV + b1;
            float2 p0 = make_float2(fmaxf(v0, 0.01f * v0), fmaxf(v1, 0.01f * v1));
            float2 p1 = make_float2(fmaxf(v2, 0.01f * v2), fmaxf(v3, 0.01f * v3));
            *(float2*)&out[(size_t)r0 * HID + col]       = p0;
            *(float2*)&out[(size_t)(r0 + 8) * HID + col] = p1;
        }
    }
}

// ---------------------------------------------------------------------------
extern "C" void kernel_launch(void* const* d_in, const int* in_sizes, int n_in,
                              void* d_out, int out_size) {
    (void)in_sizes; (void)n_in; (void)out_size;
    const int*   nodes = (const int*)  d_in[0];
    const float* emb   = (const float*)d_in[1];
    const float* adj   = (const float*)d_in[2];
    const float* W1    = (const float*)d_in[3];
    const float* b1    = (const float*)d_in[4];
    const float* W2    = (const float*)d_in[5];
    const float* b2    = (const float*)d_in[6];
    float* out = (float*)d_out;

    cudaFuncSetAttribute(big_gemm_kernel, cudaFuncAttributeMaxDynamicSharedMemorySize, SMEM_BYTES);

    size_t total = (size_t)N_NODES * N_NODES;
    int cgrid = (int)((total / 8 + 255) / 256);
    int gs = (N_NODES + 31) / 32;     // 313
    int gm = N_NODES / BM;            // 125, exact

    convert_adj_kernel<<<cgrid, 256>>>(adj);
    gather_max_kernel<<<N_NODES, 128>>>(nodes, emb);
    small_gemm_kernel<<<gs, 256>>>(W1, EMBED, 0);
    big_gemm_kernel<<<gm, 256, SMEM_BYTES>>>(b1, nullptr);   // g_h1
    small_gemm_kernel<<<gs, 256>>>(W2, HID, 1);
    big_gemm_kernel<<<gm, 256, SMEM_BYTES>>>(b2, out);
}